// round 6
// baseline (speedup 1.0000x reference)
#include <cuda_runtime.h>
#include <cuda_fp16.h>
#include <cstdint>
#include <cstddef>

#define NB 4096
#define HH 512
#define NSEQ 100
#define NJ 63
#define GRID_P 296

// ---------- device scratch ----------
__device__ __align__(1024) __half g_xh [NB * 256];
__device__ __align__(1024) __half g_h0h[2][NB * HH];
__device__ __align__(1024) __half g_h1a[(size_t)(NSEQ + 1) * NB * HH];
__device__ __align__(1024) float  g_c0 [NB * HH];
__device__ __align__(1024) float  g_c1 [NB * HH];
__device__ __align__(1024) __half g_Wi0p[16 * 128 * 256];
__device__ __align__(1024) __half g_Wp0 [16 * 128 * 512];
__device__ __align__(1024) __half g_Wp1 [16 * 128 * 1024];
__device__ float g_b0p[2048];
__device__ float g_b1p[2048];
__device__ __align__(1024) float g_x0T[(size_t)2048 * NB];
__device__ float g_y[(size_t)NSEQ * NB * NJ];
__device__ unsigned g_bar;
__device__ unsigned g_tick[NSEQ + 1];

// ---------- helpers ----------
__device__ __forceinline__ float sigm(float x) { return 1.f / (1.f + expf(-x)); }
__device__ __forceinline__ uint32_t smem_u32(const void* p) {
    uint32_t a;
    asm("{ .reg .u64 t; cvta.to.shared.u64 t, %1; cvt.u32.u64 %0, t; }" : "=r"(a) : "l"(p));
    return a;
}
__device__ __forceinline__ float ldcg_f(const float* p) {
    float v; asm volatile("ld.global.cg.f32 %0, [%1];" : "=f"(v) : "l"(p)); return v;
}
__device__ __forceinline__ void stcg_f(float* p, float v) {
    asm volatile("st.global.cg.f32 [%0], %1;" :: "l"(p), "f"(v));
}
__device__ __forceinline__ void stcg_h(__half* p, __half v) {
    unsigned short u = __half_as_ushort(v);
    asm volatile("st.global.cg.u16 [%0], %1;" :: "l"(p), "h"(u));
}
#define CP16(dst, src) asm volatile("cp.async.cg.shared.global [%0], [%1], 16;" :: "r"((uint32_t)(dst)), "l"(src) : "memory")
#define CP_COMMIT()    asm volatile("cp.async.commit_group;" ::: "memory")
#define CP_WAIT(n)     asm volatile("cp.async.wait_group %0;" :: "n"(n) : "memory")
#define LDSM_X4(r0, r1, r2, r3, a) \
    asm volatile("ldmatrix.sync.aligned.m8n8.x4.shared.b16 {%0,%1,%2,%3}, [%4];" \
        : "=r"(r0), "=r"(r1), "=r"(r2), "=r"(r3) : "r"(a))

__device__ __forceinline__ void hmma(float (&c)[4],
    uint32_t a0, uint32_t a1, uint32_t a2, uint32_t a3, uint32_t b0, uint32_t b1)
{
    asm volatile(
        "mma.sync.aligned.m16n8k16.row.col.f32.f16.f16.f32 "
        "{%0,%1,%2,%3}, {%4,%5,%6,%7}, {%8,%9}, {%0,%1,%2,%3};\n"
        : "+f"(c[0]), "+f"(c[1]), "+f"(c[2]), "+f"(c[3])
        : "r"(a0), "r"(a1), "r"(a2), "r"(a3), "r"(b0), "r"(b1));
}
__device__ __forceinline__ uint32_t sw128(uint32_t off) { return off ^ ((off >> 3) & 0x70); }

// ---------- prologue (R5 packing: col n of tile jt -> orig row (n&3)*512 + jt*32 + (n>>2)) ----------
__global__ void pack_weights(
    const float* __restrict__ Wih0, const float* __restrict__ Whh0,
    const float* __restrict__ bih0, const float* __restrict__ bhh0,
    const float* __restrict__ Wih1, const float* __restrict__ Whh1,
    const float* __restrict__ bih1, const float* __restrict__ bhh1)
{
    int i0 = blockIdx.x * blockDim.x + threadIdx.x;
    int st = gridDim.x * blockDim.x;
    for (int i = i0; i < 16 * 128 * 512; i += st) {
        int jt = i >> 16, n = (i >> 9) & 127, k = i & 511;
        int row = (n & 3) * HH + jt * 32 + (n >> 2);
        g_Wp0[i] = __float2half_rn(Whh0[(size_t)row * HH + k]);
    }
    for (int i = i0; i < 16 * 128 * 1024; i += st) {
        int jt = i >> 17, n = (i >> 10) & 127, k = i & 1023;
        int row = (n & 3) * HH + jt * 32 + (n >> 2);
        float v = (k < HH) ? Wih1[(size_t)row * HH + k] : Whh1[(size_t)row * HH + k - HH];
        g_Wp1[i] = __float2half_rn(v);
    }
    for (int i = i0; i < 16 * 128 * 256; i += st) {
        int jt = i >> 15, n = (i >> 8) & 127, k = i & 255;
        int row = (n & 3) * HH + jt * 32 + (n >> 2);
        g_Wi0p[i] = (k < 254) ? __float2half_rn(Wih0[(size_t)row * 254 + k]) : __half(0);
    }
    for (int i = i0; i < 2048; i += st) {
        int jt = i >> 7, n = i & 127;
        int row = (n & 3) * HH + jt * 32 + (n >> 2);
        g_b0p[i] = bih0[row] + bhh0[row];
        g_b1p[i] = bih1[row] + bhh1[row];
    }
}

__global__ void build_x_init(
    const int* __restrict__ sl, const int* __restrict__ el,
    const float* __restrict__ sc, const float* __restrict__ ec,
    const float* __restrict__ emb)
{
    int i0 = blockIdx.x * blockDim.x + threadIdx.x;
    int st = gridDim.x * blockDim.x;
    if (i0 == 0) g_bar = 0u;
    for (int i = i0; i <= NSEQ; i += st) g_tick[i] = 0u;
    for (int i = i0; i < NB * 256; i += st) {
        int b = i >> 8, k = i & 255;
        float v;
        if      (k < 64)  v = emb[sl[b] * 64 + k];
        else if (k < 128) v = emb[el[b] * 64 + (k - 64)];
        else if (k < 191) v = sc[b * 63 + (k - 128)];
        else if (k < 254) v = ec[b * 63 + (k - 191)];
        else              v = 0.f;
        g_xh[i] = __float2half_rn(v);
    }
    __half z = __half(0);
    for (int i = i0; i < NB * HH; i += st) {
        g_h0h[0][i] = z; g_h0h[1][i] = z; g_h1a[i] = z;
        g_c0[i] = 0.f; g_c1[i] = 0.f;
    }
}

// ---------- fused GEMM + gates tile ----------
// CTA tile 128x128 (4 gates x 32 units interleaved), 8 warps (4 row x 2 col), warp 32x64.
// 3-stage cp.async pipeline, prefetch distance 2, one __syncthreads per chunk.
constexpr int STGB = 32768;
constexpr int SMEMSZ = 3 * STGB + 16;

template<int MODE>   // 0: layer0 K=512 (+x0T)  1: layer1 K=1024 (+bias)  2: x0 K=256 (+bias)
__device__ __forceinline__ void tile_body(
    const __half* __restrict__ A1, const __half* __restrict__ A2,
    const __half* __restrict__ Wp, const float* __restrict__ addv,
    float* __restrict__ cbuf, void* __restrict__ houtv, char* smem, int m0, int jt)
{
    const uint32_t sb = smem_u32(smem);
    const int tid = threadIdx.x, lane = tid & 31, wid = tid >> 5;
    const int wr = wid & 3, wc = wid >> 2;
    constexpr int KW  = (MODE == 0) ? 512 : (MODE == 1) ? 1024 : 256;
    constexpr int LDA = (MODE == 2) ? 256 : 512;
    constexpr int NT  = KW / 64;

    const __half* Bb = Wp + (size_t)jt * 128 * KW;

    auto copy_stage = [&](int s, int kt) {
        const uint32_t ab = sb + s * STGB, bbs = ab + 16384;
        const int k0 = kt * 64;
#pragma unroll
        for (int i = 0; i < 4; ++i) {
            int idx = tid + i * 256;
            int row = idx >> 3, ck = idx & 7;
            uint32_t sw = sw128(row * 128 + ck * 16);
            const __half* As = (MODE == 1 && k0 >= 512)
                ? A2 + (size_t)(m0 + row) * LDA + (k0 - 512) + ck * 8
                : A1 + (size_t)(m0 + row) * LDA + k0 + ck * 8;
            CP16(ab + sw, As);
            CP16(bbs + sw, Bb + (size_t)row * KW + k0 + ck * 8);
        }
    };

    float acc[2][8][4];
#pragma unroll
    for (int mt = 0; mt < 2; ++mt)
#pragma unroll
        for (int nt = 0; nt < 8; ++nt)
#pragma unroll
            for (int e = 0; e < 4; ++e) acc[mt][nt][e] = 0.f;

    copy_stage(0, 0); CP_COMMIT();
    copy_stage(1, 1); CP_COMMIT();

    const int q = lane >> 3, rr = lane & 7;
    int scur = 0;
    for (int kt = 0; kt < NT; ++kt) {
        if (kt < NT - 1) CP_WAIT(1); else CP_WAIT(0);
        __syncthreads();
        if (kt + 2 < NT) {
            int spf = scur + 2; if (spf >= 3) spf -= 3;
            copy_stage(spf, kt + 2);
            CP_COMMIT();
        }
        const uint32_t ab = sb + scur * STGB, bbs = ab + 16384;
#pragma unroll
        for (int ks = 0; ks < 4; ++ks) {
            uint32_t a[2][4];
#pragma unroll
            for (int mt = 0; mt < 2; ++mt)
                LDSM_X4(a[mt][0], a[mt][1], a[mt][2], a[mt][3],
                    ab + sw128((wr * 32 + mt * 16 + (q & 1) * 8 + rr) * 128 + ks * 32 + (q >> 1) * 16));
#pragma unroll
            for (int nt2 = 0; nt2 < 4; ++nt2) {
                uint32_t b0, b1, b2, b3;
                LDSM_X4(b0, b1, b2, b3,
                    bbs + sw128((wc * 64 + nt2 * 16 + (q >> 1) * 8 + rr) * 128 + ks * 32 + (q & 1) * 16));
#pragma unroll
                for (int mt = 0; mt < 2; ++mt) {
                    hmma(acc[mt][nt2 * 2 + 0], a[mt][0], a[mt][1], a[mt][2], a[mt][3], b0, b1);
                    hmma(acc[mt][nt2 * 2 + 1], a[mt][0], a[mt][1], a[mt][2], a[mt][3], b2, b3);
                }
            }
        }
        if (++scur == 3) scur = 0;
    }

    // ---------- epilogue ----------
    const int q4 = lane & 3;
    const int rbase = m0 + wr * 32 + (lane >> 2);

#pragma unroll
    for (int mt = 0; mt < 2; ++mt)
#pragma unroll
        for (int nt = 0; nt < 8; ++nt) {
            float* a = acc[mt][nt];
            const int cc = wc * 64 + nt * 8 + q4 * 2;
            const int ng = jt * 128 + cc;
            const int r0 = rbase + mt * 16, r1 = r0 + 8;
            if (MODE == 0) {
                const float* xp  = addv + (size_t)ng * NB;
                const float* xp1 = xp + NB;
                a[0] += xp[r0]; a[1] += xp1[r0]; a[2] += xp[r1]; a[3] += xp1[r1];
            } else {
                float b0 = addv[ng], b1 = addv[ng + 1];
                a[0] += b0; a[1] += b1; a[2] += b0; a[3] += b1;
            }
            if (MODE == 2) {
                float* x0T = (float*)houtv;
                x0T[(size_t)ng * NB + r0]       = a[0];
                x0T[(size_t)(ng + 1) * NB + r0] = a[1];
                x0T[(size_t)ng * NB + r1]       = a[2];
                x0T[(size_t)(ng + 1) * NB + r1] = a[3];
            } else {
                float t0 = __shfl_xor_sync(0xffffffffu, a[0], 1);
                float t1 = __shfl_xor_sync(0xffffffffu, a[1], 1);
                float t2 = __shfl_xor_sync(0xffffffffu, a[2], 1);
                float t3 = __shfl_xor_sync(0xffffffffu, a[3], 1);
                float pi, pf, pg, po;
                int row;
                if (q4 & 1) { pi = t2;   pf = t3;   pg = a[2]; po = a[3]; row = r1; }
                else        { pi = a[0]; pf = a[1]; pg = t0;   po = t1;   row = r0; }
                const int u = jt * 32 + (cc >> 2);
                float* cp = cbuf + (size_t)row * HH + u;
                float co = ldcg_f(cp);
                float cv = sigm(pf) * co + sigm(pi) * tanhf(pg);
                stcg_f(cp, cv);
                stcg_h((__half*)houtv + (size_t)row * HH + u,
                       __float2half_rn(sigm(po) * tanhf(cv)));
            }
        }
}

// ---------- x0 build (one-shot) ----------
__global__ void __launch_bounds__(256, 2) x0_step()
{
    extern __shared__ char smem[];
    tile_body<2>(g_xh, nullptr, g_Wi0p, g_b0p, nullptr, g_x0T, smem,
                 blockIdx.x * 128, blockIdx.y);
}

// ---------- grid barrier ----------
__device__ __forceinline__ void gsync(unsigned target)
{
    __syncthreads();
    if (threadIdx.x == 0) {
        __threadfence();
        atomicAdd(&g_bar, 1u);
        unsigned spins = 0;
        while (*(volatile unsigned*)&g_bar < target) {
            if (++spins > 20000000u) break;   // bailout -> visible failure, not hang
            __nanosleep(64);
        }
    }
    __syncthreads();
}

// ---------- persistent LSTM: 101 iterations, ticketed tiles, 1 barrier/iter ----------
__global__ void __launch_bounds__(256, 2) persistent_lstm()
{
    extern __shared__ char smem[];
    unsigned* tick = (unsigned*)(smem + 3 * STGB);
    const size_t NH = (size_t)NB * HH;

    for (int i = 0; i <= NSEQ; ++i) {
        for (;;) {
            __syncthreads();
            if (threadIdx.x == 0) *tick = atomicAdd(&g_tick[i], 1u);
            __syncthreads();
            unsigned t = *tick;
            if (t >= 1024u) break;
            if (t < 512u) {            // layer1 for step i-1 (heavy, scheduled first)
                if (i >= 1) {
                    int m0 = (int)(t >> 4) * 128, jt = (int)(t & 15);
                    tile_body<1>(g_h0h[(i - 1) & 1], g_h1a + (size_t)(i - 1) * NH,
                                 g_Wp1, g_b1p, g_c1,
                                 g_h1a + (size_t)i * NH, smem, m0, jt);
                }
            } else {                   // layer0 for step i
                if (i < NSEQ) {
                    unsigned s = t - 512u;
                    int m0 = (int)(s >> 4) * 128, jt = (int)(s & 15);
                    tile_body<0>(g_h0h[(i + 1) & 1], nullptr,
                                 g_Wp0, g_x0T, g_c0,
                                 g_h0h[i & 1], smem, m0, jt);
                }
            }
        }
        gsync((unsigned)(i + 1) * GRID_P);
    }
}

// ---------- batched fc over all timesteps ----------
__global__ void fc_all(const __half* __restrict__ h1, const float* __restrict__ fcW,
                       const float* __restrict__ fcb, float* __restrict__ yout)
{
    __shared__ float sh[64 * 33];
    __shared__ float sw[64 * 33];
    const int tid = threadIdx.x;
    const size_t r0 = (size_t)blockIdx.x * 64;
    const int rs = tid & 15, cg = tid >> 4;
    float acc[4][4];
#pragma unroll
    for (int r = 0; r < 4; ++r)
#pragma unroll
        for (int c = 0; c < 4; ++c) acc[r][c] = 0.f;

    for (int k0 = 0; k0 < HH; k0 += 32) {
        {
            int rr = tid >> 2, seg = tid & 3;
            uint4 v = *reinterpret_cast<const uint4*>(&h1[(r0 + rr) * HH + k0 + seg * 8]);
            const __half2* hp = reinterpret_cast<const __half2*>(&v);
            float* d = &sh[rr * 33 + seg * 8];
#pragma unroll
            for (int m = 0; m < 4; ++m) {
                float2 f = __half22float2(hp[m]);
                d[2 * m] = f.x; d[2 * m + 1] = f.y;
            }
        }
        for (int q2 = tid; q2 < 64 * 32; q2 += 256) {
            int j = q2 >> 5, kk = q2 & 31;
            sw[j * 33 + kk] = (j < NJ) ? fcW[(size_t)j * HH + k0 + kk] : 0.f;
        }
        __syncthreads();
#pragma unroll
        for (int kk = 0; kk < 32; ++kk) {
            float hv[4], wv[4];
#pragma unroll
            for (int r = 0; r < 4; ++r) hv[r] = sh[(rs + r * 16) * 33 + kk];
#pragma unroll
            for (int c = 0; c < 4; ++c) wv[c] = sw[(cg * 4 + c) * 33 + kk];
#pragma unroll
            for (int r = 0; r < 4; ++r)
#pragma unroll
                for (int c = 0; c < 4; ++c) acc[r][c] += hv[r] * wv[c];
        }
        __syncthreads();
    }
#pragma unroll
    for (int r = 0; r < 4; ++r)
#pragma unroll
        for (int c = 0; c < 4; ++c) {
            int jj = cg * 4 + c;
            if (jj < NJ)
                yout[(r0 + rs + r * 16) * NJ + jj] = acc[r][c] + fcb[jj];
        }
}

// ---------- final transpose [t][b][j] -> [b][j][t] ----------
__global__ void transpose_y(const float* __restrict__ gy, float* __restrict__ out)
{
    __shared__ float sy[NSEQ * NJ];
    const int b = blockIdx.x;
    for (int q = threadIdx.x; q < NSEQ * NJ; q += blockDim.x)
        sy[q] = gy[(size_t)(q / NJ) * NB * NJ + (size_t)b * NJ + (q % NJ)];
    __syncthreads();
    for (int q = threadIdx.x; q < NSEQ * NJ; q += blockDim.x) {
        int j = q / NSEQ, t = q - j * NSEQ;
        out[(size_t)b * (NJ * NSEQ) + q] = sy[t * NJ + j];
    }
}

// ---------- host ----------
template <typename T>
static void* symaddr(T& sym) {
    void* p = nullptr;
    cudaGetSymbolAddress(&p, sym);
    return p;
}

extern "C" void kernel_launch(void* const* d_in, const int* in_sizes, int n_in,
                              void* d_out, int out_size)
{
    const int*   sl   = (const int*)  d_in[0];
    const int*   el   = (const int*)  d_in[1];
    const float* sc   = (const float*)d_in[2];
    const float* ec   = (const float*)d_in[3];
    const float* emb  = (const float*)d_in[4];
    const float* Wih0 = (const float*)d_in[5];
    const float* Whh0 = (const float*)d_in[6];
    const float* bih0 = (const float*)d_in[7];
    const float* bhh0 = (const float*)d_in[8];
    const float* Wih1 = (const float*)d_in[9];
    const float* Whh1 = (const float*)d_in[10];
    const float* bih1 = (const float*)d_in[11];
    const float* bhh1 = (const float*)d_in[12];
    const float* fcW  = (const float*)d_in[13];
    const float* fcb  = (const float*)d_in[14];
    float* out = (float*)d_out;

    __half* p_h1a = (__half*)symaddr(g_h1a);
    float*  p_y   = (float*) symaddr(g_y);

    cudaFuncSetAttribute(x0_step,         cudaFuncAttributeMaxDynamicSharedMemorySize, SMEMSZ);
    cudaFuncSetAttribute(persistent_lstm, cudaFuncAttributeMaxDynamicSharedMemorySize, SMEMSZ);

    pack_weights<<<256, 256>>>(Wih0, Whh0, bih0, bhh0, Wih1, Whh1, bih1, bhh1);
    build_x_init<<<256, 256>>>(sl, el, sc, ec, emb);

    x0_step<<<dim3(32, 16, 1), 256, SMEMSZ>>>();
    persistent_lstm<<<GRID_P, 256, SMEMSZ>>>();

    const size_t NH = (size_t)NB * HH;
    fc_all<<<NSEQ * 64, 256>>>(p_h1a + NH, fcW, fcb, p_y);
    transpose_y<<<NB, 256>>>(p_y, out);
}

// round 7
// speedup vs baseline: 1.5952x; 1.5952x over previous
#include <cuda_runtime.h>
#include <cuda_fp16.h>
#include <cstdint>
#include <cstddef>

#define NB 4096
#define HH 512
#define NSEQ 100
#define NJ 63

// ---------- device scratch ----------
__device__ __align__(1024) __half g_xh [NB * 256];
__device__ __align__(1024) __half g_h0h[2][NB * HH];
__device__ __align__(1024) __half g_h1a[(size_t)(NSEQ + 1) * NB * HH];
__device__ __align__(1024) float  g_c0 [NB * HH];      // gate-order layout
__device__ __align__(1024) float  g_c1 [NB * HH];      // gate-order layout
__device__ __align__(1024) __half g_Wi0p[16 * 128 * 256];
__device__ __align__(1024) __half g_Wp0 [16 * 128 * 512];
__device__ __align__(1024) __half g_Wp1 [16 * 128 * 1024];
__device__ float g_b0p[2048];
__device__ float g_b1p[2048];
__device__ __align__(1024) float g_x0T[(size_t)2048 * NB];  // gate-order layout
__device__ float g_y[(size_t)NSEQ * NB * NJ];

// ---------- helpers ----------
__device__ __forceinline__ float sigm(float x) { return 1.f / (1.f + expf(-x)); }
__device__ __forceinline__ uint32_t smem_u32(const void* p) {
    uint32_t a;
    asm("{ .reg .u64 t; cvta.to.shared.u64 t, %1; cvt.u32.u64 %0, t; }" : "=r"(a) : "l"(p));
    return a;
}
#define CP16(dst, src) asm volatile("cp.async.cg.shared.global [%0], [%1], 16;" :: "r"((uint32_t)(dst)), "l"(src) : "memory")
#define CP_COMMIT()    asm volatile("cp.async.commit_group;" ::: "memory")
#define CP_WAIT(n)     asm volatile("cp.async.wait_group %0;" :: "n"(n) : "memory")
#define LDSM_X4(r0, r1, r2, r3, a) \
    asm volatile("ldmatrix.sync.aligned.m8n8.x4.shared.b16 {%0,%1,%2,%3}, [%4];" \
        : "=r"(r0), "=r"(r1), "=r"(r2), "=r"(r3) : "r"(a))

__device__ __forceinline__ void hmma(float (&c)[4],
    uint32_t a0, uint32_t a1, uint32_t a2, uint32_t a3, uint32_t b0, uint32_t b1)
{
    asm volatile(
        "mma.sync.aligned.m16n8k16.row.col.f32.f16.f16.f32 "
        "{%0,%1,%2,%3}, {%4,%5,%6,%7}, {%8,%9}, {%0,%1,%2,%3};\n"
        : "+f"(c[0]), "+f"(c[1]), "+f"(c[2]), "+f"(c[3])
        : "r"(a0), "r"(a1), "r"(a2), "r"(a3), "r"(b0), "r"(b1));
}
__device__ __forceinline__ uint32_t sw128(uint32_t off) { return off ^ ((off >> 3) & 0x70); }

// ---------- prologue: col n of tile jt -> orig row (n&3)*512 + jt*32 + (n>>2) ----------
__global__ void pack_weights(
    const float* __restrict__ Wih0, const float* __restrict__ Whh0,
    const float* __restrict__ bih0, const float* __restrict__ bhh0,
    const float* __restrict__ Wih1, const float* __restrict__ Whh1,
    const float* __restrict__ bih1, const float* __restrict__ bhh1)
{
    int i0 = blockIdx.x * blockDim.x + threadIdx.x;
    int st = gridDim.x * blockDim.x;
    for (int i = i0; i < 16 * 128 * 512; i += st) {
        int jt = i >> 16, n = (i >> 9) & 127, k = i & 511;
        int row = (n & 3) * HH + jt * 32 + (n >> 2);
        g_Wp0[i] = __float2half_rn(Whh0[(size_t)row * HH + k]);
    }
    for (int i = i0; i < 16 * 128 * 1024; i += st) {
        int jt = i >> 17, n = (i >> 10) & 127, k = i & 1023;
        int row = (n & 3) * HH + jt * 32 + (n >> 2);
        float v = (k < HH) ? Wih1[(size_t)row * HH + k] : Whh1[(size_t)row * HH + k - HH];
        g_Wp1[i] = __float2half_rn(v);
    }
    for (int i = i0; i < 16 * 128 * 256; i += st) {
        int jt = i >> 15, n = (i >> 8) & 127, k = i & 255;
        int row = (n & 3) * HH + jt * 32 + (n >> 2);
        g_Wi0p[i] = (k < 254) ? __float2half_rn(Wih0[(size_t)row * 254 + k]) : __half(0);
    }
    for (int i = i0; i < 2048; i += st) {
        int jt = i >> 7, n = i & 127;
        int row = (n & 3) * HH + jt * 32 + (n >> 2);
        g_b0p[i] = bih0[row] + bhh0[row];
        g_b1p[i] = bih1[row] + bhh1[row];
    }
}

__global__ void build_x_init(
    const int* __restrict__ sl, const int* __restrict__ el,
    const float* __restrict__ sc, const float* __restrict__ ec,
    const float* __restrict__ emb)
{
    int i0 = blockIdx.x * blockDim.x + threadIdx.x;
    int st = gridDim.x * blockDim.x;
    for (int i = i0; i < NB * 256; i += st) {
        int b = i >> 8, k = i & 255;
        float v;
        if      (k < 64)  v = emb[sl[b] * 64 + k];
        else if (k < 128) v = emb[el[b] * 64 + (k - 64)];
        else if (k < 191) v = sc[b * 63 + (k - 128)];
        else if (k < 254) v = ec[b * 63 + (k - 191)];
        else              v = 0.f;
        g_xh[i] = __float2half_rn(v);
    }
    __half z = __half(0);
    for (int i = i0; i < NB * HH; i += st) {
        g_h0h[0][i] = z; g_h0h[1][i] = z; g_h1a[i] = z;
        g_c0[i] = 0.f; g_c1[i] = 0.f;
    }
}

// ---------- fused GEMM + gates ----------
// CTA 128x128 (gate-interleaved cols), 8 warps (4 row x 2 col), warp 32x64.
// 3-stage cp.async, distance 2, one __syncthreads per chunk.
constexpr int STGB = 32768;
constexpr int SMEMSZ = 3 * STGB;

template<int MODE>   // 0: layer0 K=512 (+x0)  1: layer1 K=1024 (+bias)  2: x0 K=256 (+bias)
__device__ __forceinline__ void tile_body(
    const __half* __restrict__ A1, const __half* __restrict__ A2,
    const __half* __restrict__ Wp, const float* __restrict__ addv,
    float* __restrict__ cbuf, void* __restrict__ houtv, char* smem,
    int m0, int jt, int tl)
{
    const uint32_t sb = smem_u32(smem);
    const int tid = threadIdx.x, lane = tid & 31, wid = tid >> 5;
    const int wr = wid & 3, wc = wid >> 2;
    constexpr int KW  = (MODE == 0) ? 512 : (MODE == 1) ? 1024 : 256;
    constexpr int LDA = (MODE == 2) ? 256 : 512;
    constexpr int NT  = KW / 64;

    const __half* Bb = Wp + (size_t)jt * 128 * KW;

    auto copy_stage = [&](int s, int kt) {
        const uint32_t ab = sb + s * STGB, bbs = ab + 16384;
        const int k0 = kt * 64;
#pragma unroll
        for (int i = 0; i < 4; ++i) {
            int idx = tid + i * 256;
            int row = idx >> 3, ck = idx & 7;
            uint32_t sw = sw128(row * 128 + ck * 16);
            const __half* As = (MODE == 1 && k0 >= 512)
                ? A2 + (size_t)(m0 + row) * LDA + (k0 - 512) + ck * 8
                : A1 + (size_t)(m0 + row) * LDA + k0 + ck * 8;
            CP16(ab + sw, As);
            CP16(bbs + sw, Bb + (size_t)row * KW + k0 + ck * 8);
        }
    };

    float acc[2][8][4];
#pragma unroll
    for (int mt = 0; mt < 2; ++mt)
#pragma unroll
        for (int nt = 0; nt < 8; ++nt)
#pragma unroll
            for (int e = 0; e < 4; ++e) acc[mt][nt][e] = 0.f;

    copy_stage(0, 0); CP_COMMIT();
    copy_stage(1, 1); CP_COMMIT();

    const int q = lane >> 3, rr = lane & 7;
    int scur = 0;
    for (int kt = 0; kt < NT; ++kt) {
        if (kt < NT - 1) CP_WAIT(1); else CP_WAIT(0);
        __syncthreads();
        if (kt + 2 < NT) {
            int spf = scur + 2; if (spf >= 3) spf -= 3;
            copy_stage(spf, kt + 2);
            CP_COMMIT();
        }
        const uint32_t ab = sb + scur * STGB, bbs = ab + 16384;
#pragma unroll
        for (int ks = 0; ks < 4; ++ks) {
            uint32_t a[2][4];
#pragma unroll
            for (int mt = 0; mt < 2; ++mt)
                LDSM_X4(a[mt][0], a[mt][1], a[mt][2], a[mt][3],
                    ab + sw128((wr * 32 + mt * 16 + (q & 1) * 8 + rr) * 128 + ks * 32 + (q >> 1) * 16));
#pragma unroll
            for (int nt2 = 0; nt2 < 4; ++nt2) {
                uint32_t b0, b1, b2, b3;
                LDSM_X4(b0, b1, b2, b3,
                    bbs + sw128((wc * 64 + nt2 * 16 + (q >> 1) * 8 + rr) * 128 + ks * 32 + (q & 1) * 16));
#pragma unroll
                for (int mt = 0; mt < 2; ++mt) {
                    hmma(acc[mt][nt2 * 2 + 0], a[mt][0], a[mt][1], a[mt][2], a[mt][3], b0, b1);
                    hmma(acc[mt][nt2 * 2 + 1], a[mt][0], a[mt][1], a[mt][2], a[mt][3], b2, b3);
                }
            }
        }
        if (++scur == 3) scur = 0;
    }

    __syncthreads();   // all warps done reading stage smem

    // ---------- epilogue (fully coalesced) ----------
    const int q4 = lane & 3;
    float* hs = (float*)smem;                       // 128 x 33 staging (reuses stages)
    float* cw = cbuf + ((size_t)(tl * 8 + wid) * 16) * 32 + lane;
    const float* x0r = g_x0T + ((size_t)(tl * 8 + wid) * 16) * 128 + lane * 4;

#pragma unroll
    for (int mt = 0; mt < 2; ++mt)
#pragma unroll
        for (int nt = 0; nt < 8; ++nt) {
            const int grp = mt * 8 + nt;
            float* a = acc[mt][nt];
            if (MODE == 0) {
                float4 xv = *reinterpret_cast<const float4*>(x0r + grp * 128);
                a[0] += xv.x; a[1] += xv.y; a[2] += xv.z; a[3] += xv.w;
            } else {
                const int ng = jt * 128 + wc * 64 + nt * 8 + q4 * 2;
                float b0 = addv[ng], b1 = addv[ng + 1];
                a[0] += b0; a[1] += b1; a[2] += b0; a[3] += b1;
            }
            if (MODE == 2) {
                float* xw = (float*)houtv + ((size_t)(tl * 8 + wid) * 16 + grp) * 128 + lane * 4;
                *reinterpret_cast<float4*>(xw) = make_float4(a[0], a[1], a[2], a[3]);
            } else {
                float t0 = __shfl_xor_sync(0xffffffffu, a[0], 1);
                float t1 = __shfl_xor_sync(0xffffffffu, a[1], 1);
                float t2 = __shfl_xor_sync(0xffffffffu, a[2], 1);
                float t3 = __shfl_xor_sync(0xffffffffu, a[3], 1);
                float pi, pf, pg, po;
                if (q4 & 1) { pi = t2;   pf = t3;   pg = a[2]; po = a[3]; }
                else        { pi = a[0]; pf = a[1]; pg = t0;   po = t1;   }
                float co = cw[grp * 32];
                float cv = sigm(pf) * co + sigm(pi) * tanhf(pg);
                cw[grp * 32] = cv;
                const int row_l = wr * 32 + mt * 16 + (lane >> 2) + (q4 & 1) * 8;
                const int u_l   = wc * 16 + nt * 2 + (q4 >> 1);
                hs[row_l * 33 + u_l] = sigm(po) * tanhf(cv);
            }
        }

    if (MODE != 2) {
        __syncthreads();
        __half* hout = (__half*)houtv;
        const int row = tid >> 1, seg = tid & 1;
        __half2 pk[8];
#pragma unroll
        for (int j = 0; j < 8; ++j)
            pk[j] = __floats2half2_rn(hs[row * 33 + seg * 16 + 2 * j],
                                      hs[row * 33 + seg * 16 + 2 * j + 1]);
        uint4* dst = reinterpret_cast<uint4*>(&hout[(size_t)(m0 + row) * HH + jt * 32 + seg * 16]);
        dst[0] = reinterpret_cast<uint4*>(pk)[0];
        dst[1] = reinterpret_cast<uint4*>(pk)[1];
        __syncthreads();
    }
}

__global__ void __launch_bounds__(256, 2) x0_step()
{
    extern __shared__ char smem[];
    tile_body<2>(g_xh, nullptr, g_Wi0p, g_b0p, nullptr, g_x0T, smem,
                 blockIdx.x * 128, blockIdx.y, blockIdx.x * 16 + blockIdx.y);
}

// z == 0 -> layer1(t); z == 1 -> layer0(t+1)   (both read h0_rd, independent)
__global__ void __launch_bounds__(256, 2) dual_step(
    const __half* __restrict__ h0_rd, __half* __restrict__ h0_wr,
    const __half* __restrict__ h1_rd, __half* __restrict__ h1_wr, int zoff)
{
    extern __shared__ char smem[];
    const int m0 = blockIdx.x * 128, jt = blockIdx.y;
    const int tl = blockIdx.x * 16 + blockIdx.y;
    if ((int)blockIdx.z + zoff == 0)
        tile_body<1>(h0_rd, h1_rd, g_Wp1, g_b1p, g_c1, h1_wr, smem, m0, jt, tl);
    else
        tile_body<0>(h0_rd, nullptr, g_Wp0, nullptr, g_c0, h0_wr, smem, m0, jt, tl);
}

// ---------- batched fc ----------
__global__ void fc_all(const __half* __restrict__ h1, const float* __restrict__ fcW,
                       const float* __restrict__ fcb, float* __restrict__ yout)
{
    __shared__ float sh[64 * 33];
    __shared__ float sw[64 * 33];
    const int tid = threadIdx.x;
    const size_t r0 = (size_t)blockIdx.x * 64;
    const int rs = tid & 15, cg = tid >> 4;
    float acc[4][4];
#pragma unroll
    for (int r = 0; r < 4; ++r)
#pragma unroll
        for (int c = 0; c < 4; ++c) acc[r][c] = 0.f;

    for (int k0 = 0; k0 < HH; k0 += 32) {
        {
            int rr = tid >> 2, seg = tid & 3;
            uint4 v = *reinterpret_cast<const uint4*>(&h1[(r0 + rr) * HH + k0 + seg * 8]);
            const __half2* hp = reinterpret_cast<const __half2*>(&v);
            float* d = &sh[rr * 33 + seg * 8];
#pragma unroll
            for (int m = 0; m < 4; ++m) {
                float2 f = __half22float2(hp[m]);
                d[2 * m] = f.x; d[2 * m + 1] = f.y;
            }
        }
        for (int q2 = tid; q2 < 64 * 32; q2 += 256) {
            int j = q2 >> 5, kk = q2 & 31;
            sw[j * 33 + kk] = (j < NJ) ? fcW[(size_t)j * HH + k0 + kk] : 0.f;
        }
        __syncthreads();
#pragma unroll
        for (int kk = 0; kk < 32; ++kk) {
            float hv[4], wv[4];
#pragma unroll
            for (int r = 0; r < 4; ++r) hv[r] = sh[(rs + r * 16) * 33 + kk];
#pragma unroll
            for (int c = 0; c < 4; ++c) wv[c] = sw[(cg * 4 + c) * 33 + kk];
#pragma unroll
            for (int r = 0; r < 4; ++r)
#pragma unroll
                for (int c = 0; c < 4; ++c) acc[r][c] += hv[r] * wv[c];
        }
        __syncthreads();
    }
#pragma unroll
    for (int r = 0; r < 4; ++r)
#pragma unroll
        for (int c = 0; c < 4; ++c) {
            int jj = cg * 4 + c;
            if (jj < NJ)
                yout[(r0 + rs + r * 16) * NJ + jj] = acc[r][c] + fcb[jj];
        }
}

// ---------- final transpose [t][b][j] -> [b][j][t] ----------
__global__ void transpose_y(const float* __restrict__ gy, float* __restrict__ out)
{
    __shared__ float sy[NSEQ * NJ];
    const int b = blockIdx.x;
    for (int q = threadIdx.x; q < NSEQ * NJ; q += blockDim.x)
        sy[q] = gy[(size_t)(q / NJ) * NB * NJ + (size_t)b * NJ + (q % NJ)];
    __syncthreads();
    for (int q = threadIdx.x; q < NSEQ * NJ; q += blockDim.x) {
        int j = q / NSEQ, t = q - j * NSEQ;
        out[(size_t)b * (NJ * NSEQ) + q] = sy[t * NJ + j];
    }
}

// ---------- host ----------
template <typename T>
static void* symaddr(T& sym) {
    void* p = nullptr;
    cudaGetSymbolAddress(&p, sym);
    return p;
}

extern "C" void kernel_launch(void* const* d_in, const int* in_sizes, int n_in,
                              void* d_out, int out_size)
{
    const int*   sl   = (const int*)  d_in[0];
    const int*   el   = (const int*)  d_in[1];
    const float* sc   = (const float*)d_in[2];
    const float* ec   = (const float*)d_in[3];
    const float* emb  = (const float*)d_in[4];
    const float* Wih0 = (const float*)d_in[5];
    const float* Whh0 = (const float*)d_in[6];
    const float* bih0 = (const float*)d_in[7];
    const float* bhh0 = (const float*)d_in[8];
    const float* Wih1 = (const float*)d_in[9];
    const float* Whh1 = (const float*)d_in[10];
    const float* bih1 = (const float*)d_in[11];
    const float* bhh1 = (const float*)d_in[12];
    const float* fcW  = (const float*)d_in[13];
    const float* fcb  = (const float*)d_in[14];
    float* out = (float*)d_out;

    __half* p_h0h = (__half*)symaddr(g_h0h);
    __half* p_h1a = (__half*)symaddr(g_h1a);
    float*  p_y   = (float*) symaddr(g_y);

    cudaFuncSetAttribute(x0_step,   cudaFuncAttributeMaxDynamicSharedMemorySize, SMEMSZ);
    cudaFuncSetAttribute(dual_step, cudaFuncAttributeMaxDynamicSharedMemorySize, SMEMSZ);

    pack_weights<<<256, 256>>>(Wih0, Whh0, bih0, bhh0, Wih1, Whh1, bih1, bhh1);
    build_x_init<<<256, 256>>>(sl, el, sc, ec, emb);

    const size_t NH = (size_t)NB * HH;
    x0_step<<<dim3(32, 16, 1), 256, SMEMSZ>>>();

    // L0(0): reads h0h[0] (zeros), writes h0h[1]
    dual_step<<<dim3(32, 16, 1), 256, SMEMSZ>>>(p_h0h, p_h0h + NH, nullptr, nullptr, 1);

    for (int t = 0; t < NSEQ - 1; ++t) {
        const int src = (t & 1) ^ 1;
        dual_step<<<dim3(32, 16, 2), 256, SMEMSZ>>>(
            p_h0h + (size_t)src * NH,
            p_h0h + (size_t)(t & 1) * NH,
            p_h1a + (size_t)t * NH,
            p_h1a + (size_t)(t + 1) * NH, 0);
    }
    dual_step<<<dim3(32, 16, 1), 256, SMEMSZ>>>(
        p_h0h, nullptr, p_h1a + (size_t)(NSEQ - 1) * NH, p_h1a + (size_t)NSEQ * NH, 0);

    fc_all<<<NSEQ * 64, 256>>>(p_h1a + NH, fcW, fcb, p_y);
    transpose_y<<<NB, 256>>>(p_y, out);
}